// round 4
// baseline (speedup 1.0000x reference)
#include <cuda_runtime.h>
#include <math.h>

#define NLV 50000
#define NPV 150000
#define EV  500000
#define NGV 256

// ---------------- device-global scratch (module-load allocated; no runtime alloc) ----
__device__ float g_xl   [NLV*128];
__device__ float g_xl2  [NLV*128];
__device__ float g_xlsum[NLV*128];
__device__ float g_prel [NLV*128];
__device__ float g_xp   [NPV*128];
__device__ float g_xp2  [NPV*128];
__device__ float g_xpsum[NPV*128];
__device__ float g_prep [NPV*128];
__device__ float g_rbf  [EV*8];
__device__ float g_A    [(size_t)NLV*512];
__device__ float g_B    [(size_t)NPV*512];
__device__ float g_cvec [512];
__device__ int   g_dst_cnt[NPV];
__device__ int   g_dst_ptr[NPV+1];
__device__ int   g_dst_edges[EV];
__device__ int   g_src_cnt[NLV];
__device__ int   g_src_ptr[NLV+1];
__device__ int   g_src_edges[EV];
__device__ int   g_scan_tmp[NPV];
__device__ int   g_bsum[512];
__device__ float g_out_w  [NGV*128];
__device__ float g_out_max[NGV*128];

// ---------------- helpers ----------------
__device__ __forceinline__ void atomicMaxFloat(float* addr, float v) {
    if (v >= 0.0f) atomicMax((int*)addr, __float_as_int(v));
    else           atomicMin((unsigned int*)addr, __float_as_uint(v));
}

// ---------------- node embedding: Y[M,128] = X[M,44] @ Wnode[44,128] --------------
__global__ void k_embed(const float* __restrict__ X, float* __restrict__ Y,
                        const float* __restrict__ Wn, int M) {
    __shared__ float xs[4][44];
    int r0 = blockIdx.x * 4;
    int tid = threadIdx.x;  // 128
    for (int i = tid; i < 4 * 44; i += 128) {
        int rr = i / 44, kk = i % 44;
        xs[rr][kk] = (r0 + rr < M) ? X[(size_t)(r0 + rr) * 44 + kk] : 0.f;
    }
    __syncthreads();
    int col = tid;
    #pragma unroll
    for (int rr = 0; rr < 4; rr++) {
        if (r0 + rr < M) {
            float s = 0.f;
            #pragma unroll
            for (int kk = 0; kk < 44; kk++) s = fmaf(xs[rr][kk], Wn[kk * 128 + col], s);
            Y[(size_t)(r0 + rr) * 128 + col] = s;
        }
    }
}

// ---------------- RBF: mu_k = 5k/7, 1/sigma = 1.6 --------------------------------
__global__ void k_rbf(const float* __restrict__ ea) {
    int e = blockIdx.x * 256 + threadIdx.x;
    if (e < EV) {
        float d = ea[e];
        #pragma unroll
        for (int k = 0; k < 8; k++) {
            float t = (d - (5.0f / 7.0f) * (float)k) * 1.6f;
            g_rbf[e * 8 + k] = __expf(-t * t);
        }
    }
}

// ---------------- CSR construction ----------------
__global__ void k_hist(const int* __restrict__ src, const int* __restrict__ dst) {
    int e = blockIdx.x * 256 + threadIdx.x;
    if (e < EV) {
        atomicAdd(&g_dst_cnt[dst[e]], 1);
        atomicAdd(&g_src_cnt[src[e]], 1);
    }
}
__global__ void k_scan1(const int* __restrict__ cnt, int* __restrict__ excl,
                        int* __restrict__ bsum, int n) {
    __shared__ int s[1024];
    int i = blockIdx.x * 1024 + threadIdx.x;
    int v = (i < n) ? cnt[i] : 0;
    s[threadIdx.x] = v;
    __syncthreads();
    for (int off = 1; off < 1024; off <<= 1) {
        int t = 0;
        if ((int)threadIdx.x >= off) t = s[threadIdx.x - off];
        __syncthreads();
        s[threadIdx.x] += t;
        __syncthreads();
    }
    if (i < n) excl[i] = s[threadIdx.x] - v;
    if (threadIdx.x == 1023) bsum[blockIdx.x] = s[1023];
}
__global__ void k_scan2(int* bsum, int nb) {
    if (threadIdx.x == 0 && blockIdx.x == 0) {
        int acc = 0;
        for (int b = 0; b < nb; b++) { int t = bsum[b]; bsum[b] = acc; acc += t; }
    }
}
__global__ void k_scan3(const int* __restrict__ excl, const int* __restrict__ bsum,
                        int* __restrict__ ptr, int n) {
    int i = blockIdx.x * 1024 + threadIdx.x;
    if (i < n) ptr[i] = excl[i] + bsum[i >> 10];
    if (i == 0) ptr[n] = EV;
}
__global__ void k_fill(const int* __restrict__ src, const int* __restrict__ dst) {
    int e = blockIdx.x * 256 + threadIdx.x;
    if (e < EV) {
        int d = dst[e]; int p = atomicAdd(&g_dst_cnt[d], 1); g_dst_edges[g_dst_ptr[d] + p] = e;
        int s = src[e]; int q = atomicAdd(&g_src_cnt[s], 1); g_src_edges[g_src_ptr[s] + q] = e;
    }
}

// ---------------- aggregation: pre[w] = mean_e silu(rbf@Wb+bb) * xsrc[partner(e)] --
__global__ __launch_bounds__(256) void k_agg(
    const int* __restrict__ ptr, const int* __restrict__ eidx,
    const int* __restrict__ partner, const float* __restrict__ xsrc,
    const float* __restrict__ Wb_i, const float* __restrict__ bb_i,
    float* __restrict__ pre, int n_dst)
{
    int w = (blockIdx.x * blockDim.x + threadIdx.x) >> 5;
    int lane = threadIdx.x & 31;
    if (w >= n_dst) return;
    float wreg[8][4], bias[4], acc[4] = {0.f, 0.f, 0.f, 0.f};
    #pragma unroll
    for (int c = 0; c < 4; c++) {
        bias[c] = bb_i[c * 32 + lane];
        #pragma unroll
        for (int k = 0; k < 8; k++) wreg[k][c] = Wb_i[k * 128 + c * 32 + lane];
    }
    int s = ptr[w], e = ptr[w + 1];
    for (int p = s; p < e; p++) {
        int ed = eidx[p];
        float rv = (lane < 8) ? g_rbf[ed * 8 + lane] : 0.f;
        float r[8];
        #pragma unroll
        for (int k = 0; k < 8; k++) r[k] = __shfl_sync(0xffffffffu, rv, k);
        const float* xr = xsrc + (size_t)partner[ed] * 128;
        #pragma unroll
        for (int c = 0; c < 4; c++) {
            float t = bias[c];
            #pragma unroll
            for (int k = 0; k < 8; k++) t = fmaf(r[k], wreg[k][c], t);
            float sg = 1.f / (1.f + __expf(-t));
            acc[c] += (t * sg) * xr[c * 32 + lane];
        }
    }
    float inv = 1.f / (float)((e - s) > 1 ? (e - s) : 1);
    #pragma unroll
    for (int c = 0; c < 4; c++) pre[(size_t)w * 128 + c * 32 + lane] = acc[c] * inv;
}

// ---------------- generic fused SGEMM ----------------
// C[M,N] = act( A0[M,K0]@W0[K0,N] + A1[M,K1]@W1[K1,N] + bias ); optional sum += C
// tile 64x128, BK=16, 256 threads, 8x4 micro. N multiple of 128, K0/K1 multiples of 16.
__global__ __launch_bounds__(256) void k_gemm(
    const float* __restrict__ A0, const float* __restrict__ W0,
    const float* __restrict__ A1, const float* __restrict__ W1,
    const float* __restrict__ bias, float* __restrict__ C,
    float* __restrict__ sum, int M, int N, int K0, int K1, int act)
{
    __shared__ float As[16][68];
    __shared__ float Ws[16][128];
    int tid = threadIdx.x;
    int m0 = blockIdx.y * 64;
    int n0 = blockIdx.x * 128;
    int K = K0 + K1;
    float acc[8][4];
    #pragma unroll
    for (int r = 0; r < 8; r++)
        #pragma unroll
        for (int c = 0; c < 4; c++) acc[r][c] = 0.f;

    int le = tid >> 2;
    int lk = (tid & 3) * 4;
    int arow = m0 + le;
    int ty = tid >> 5, tx = tid & 31;
    int wr = tid >> 7, wc = tid & 127;

    for (int k = 0; k < K; k += 16) {
        const float* Ab; const float* Wb_; int kl; int stride;
        if (k < K0) { Ab = A0; Wb_ = W0; kl = k; stride = K0; }
        else        { Ab = A1; Wb_ = W1; kl = k - K0; stride = K1; }
        float4 a4 = make_float4(0.f, 0.f, 0.f, 0.f);
        if (arow < M) a4 = *(const float4*)(Ab + (size_t)arow * stride + kl + lk);
        As[lk + 0][le] = a4.x; As[lk + 1][le] = a4.y;
        As[lk + 2][le] = a4.z; As[lk + 3][le] = a4.w;
        #pragma unroll
        for (int i = 0; i < 8; i++) {
            int r = wr + 2 * i;
            Ws[r][wc] = Wb_[(size_t)(kl + r) * N + n0 + wc];
        }
        __syncthreads();
        #pragma unroll
        for (int kk = 0; kk < 16; kk++) {
            float4 v0 = *(const float4*)&As[kk][ty * 8];
            float4 v1 = *(const float4*)&As[kk][ty * 8 + 4];
            float a[8] = {v0.x, v0.y, v0.z, v0.w, v1.x, v1.y, v1.z, v1.w};
            float b[4];
            #pragma unroll
            for (int c = 0; c < 4; c++) b[c] = Ws[kk][tx + 32 * c];
            #pragma unroll
            for (int r = 0; r < 8; r++)
                #pragma unroll
                for (int c = 0; c < 4; c++) acc[r][c] = fmaf(a[r], b[c], acc[r][c]);
        }
        __syncthreads();
    }
    #pragma unroll
    for (int r = 0; r < 8; r++) {
        int row = m0 + ty * 8 + r;
        if (row < M) {
            #pragma unroll
            for (int c = 0; c < 4; c++) {
                int col = n0 + tx + 32 * c;
                float v = acc[r][c];
                if (bias) v += bias[col];
                if (act == 1) v = (v >= 0.f) ? v : 0.01f * v;
                C[(size_t)row * N + col] = v;
                if (sum) sum[(size_t)row * N + col] += v;
            }
        }
    }
}

// ---------------- cvec[j] = sum_k W_el[k] * W1[256+k][j] ----------------
__global__ void k_cvec(const float* __restrict__ W_el, const float* __restrict__ W1) {
    int j = blockIdx.x * 256 + threadIdx.x;
    if (j < 512) {
        float s = 0.f;
        #pragma unroll
        for (int k = 0; k < 8; k++) s = fmaf(W_el[k], W1[(size_t)(256 + k) * 512 + j], s);
        g_cvec[j] = s;
    }
}

__global__ void k_init_out() {
    int i = blockIdx.x * 256 + threadIdx.x;
    if (i < NGV * 128) { g_out_w[i] = 0.f; g_out_max[i] = -INFINITY; }
}

// ---------------- fused edge MLP + per-graph reduction ----------------
// per tile of 64 edges (src-CSR order, batch-monotone):
//   h[e,k] = relu(A[src][k] + B[dst][k] + d_e*cvec[k])   (k<512, b1 folded into A)
//   m = h @ W2 + b2 ; w = tanh(m @ Wm + bm)
//   out_w[g] += w*m (segmented) ; out_max[g] = max(m)
__global__ __launch_bounds__(256) void k_edge(
    const float* __restrict__ Al, const float* __restrict__ Bp,
    const float* __restrict__ W2, const float* __restrict__ b2,
    const float* __restrict__ Wm, const float* __restrict__ bm,
    const int* __restrict__ src, const int* __restrict__ dst,
    const float* __restrict__ ea, const int* __restrict__ lbatch)
{
    __shared__ float As[16][68];
    __shared__ float Ws[16][128];
    __shared__ float sm[64][129];
    __shared__ int se_a[64], se_b[64], se_g[64];
    __shared__ float se_d[64];
    __shared__ float cs[512];

    int tid = threadIdx.x;
    int t0 = blockIdx.x * 64;
    if (tid < 64) {
        int slot = t0 + tid;
        if (slot < EV) {
            int e = g_src_edges[slot];
            int s = src[e];
            se_a[tid] = s; se_b[tid] = dst[e];
            se_d[tid] = ea[e];
            se_g[tid] = lbatch[s];
        } else { se_a[tid] = 0; se_b[tid] = 0; se_d[tid] = 0.f; se_g[tid] = -1; }
    }
    for (int i = tid; i < 512; i += 256) cs[i] = g_cvec[i];
    __syncthreads();

    int le = tid >> 2;
    int lk = (tid & 3) * 4;
    const float* arow = Al + (size_t)se_a[le] * 512;
    const float* brow = Bp + (size_t)se_b[le] * 512;
    float dv = se_d[le];

    int ty = tid >> 5, tx = tid & 31;
    int eb = ty * 8;
    int wr = tid >> 7, wc = tid & 127;

    float acc[8][4];
    #pragma unroll
    for (int r = 0; r < 8; r++)
        #pragma unroll
        for (int c = 0; c < 4; c++) acc[r][c] = 0.f;

    // ---- GEMM 1: m = h @ W2, h built on the fly ----
    for (int k = 0; k < 512; k += 16) {
        float4 a4 = *(const float4*)(arow + k + lk);
        float4 b4 = *(const float4*)(brow + k + lk);
        float4 c4 = *(const float4*)(cs + k + lk);
        As[lk + 0][le] = fmaxf(a4.x + b4.x + dv * c4.x, 0.f);
        As[lk + 1][le] = fmaxf(a4.y + b4.y + dv * c4.y, 0.f);
        As[lk + 2][le] = fmaxf(a4.z + b4.z + dv * c4.z, 0.f);
        As[lk + 3][le] = fmaxf(a4.w + b4.w + dv * c4.w, 0.f);
        #pragma unroll
        for (int i = 0; i < 8; i++) {
            int r = wr + 2 * i;
            Ws[r][wc] = W2[(size_t)(k + r) * 128 + wc];
        }
        __syncthreads();
        #pragma unroll
        for (int kk = 0; kk < 16; kk++) {
            float4 v0 = *(const float4*)&As[kk][eb];
            float4 v1 = *(const float4*)&As[kk][eb + 4];
            float a[8] = {v0.x, v0.y, v0.z, v0.w, v1.x, v1.y, v1.z, v1.w};
            float b[4];
            #pragma unroll
            for (int c = 0; c < 4; c++) b[c] = Ws[kk][tx + 32 * c];
            #pragma unroll
            for (int r = 0; r < 8; r++)
                #pragma unroll
                for (int c = 0; c < 4; c++) acc[r][c] = fmaf(a[r], b[c], acc[r][c]);
        }
        __syncthreads();
    }

    // m = acc + b2 ; keep in regs and stage to shared for the second GEMM
    float m[8][4];
    #pragma unroll
    for (int r = 0; r < 8; r++)
        #pragma unroll
        for (int c = 0; c < 4; c++) {
            m[r][c] = acc[r][c] + b2[tx + 32 * c];
            sm[eb + r][tx + 32 * c] = m[r][c];
            acc[r][c] = 0.f;
        }
    __syncthreads();

    // ---- GEMM 2: w = tanh(m @ Wm + bm) ----
    for (int k = 0; k < 128; k += 16) {
        #pragma unroll
        for (int i = 0; i < 8; i++) {
            int r = wr + 2 * i;
            Ws[r][wc] = Wm[(size_t)(k + r) * 128 + wc];
        }
        __syncthreads();
        #pragma unroll
        for (int kk = 0; kk < 16; kk++) {
            float b[4];
            #pragma unroll
            for (int c = 0; c < 4; c++) b[c] = Ws[kk][tx + 32 * c];
            #pragma unroll
            for (int r = 0; r < 8; r++) {
                float a = sm[eb + r][k + kk];
                #pragma unroll
                for (int c = 0; c < 4; c++) acc[r][c] = fmaf(a, b[c], acc[r][c]);
            }
        }
        __syncthreads();
    }

    // ---- segmented per-graph reduction (edges contiguous per thread) ----
    #pragma unroll
    for (int c = 0; c < 4; c++) {
        int col = tx + 32 * c;
        float bmv = bm[col];
        float s = 0.f, mx = -INFINITY;
        int cg = se_g[eb];
        #pragma unroll
        for (int r = 0; r < 8; r++) {
            int g = se_g[eb + r];
            if (g != cg) {
                if (cg >= 0) {
                    atomicAdd(&g_out_w[cg * 128 + col], s);
                    atomicMaxFloat(&g_out_max[cg * 128 + col], mx);
                }
                cg = g; s = 0.f; mx = -INFINITY;
            }
            float w = tanhf(acc[r][c] + bmv);
            s += w * m[r][c];
            mx = fmaxf(mx, m[r][c]);
        }
        if (cg >= 0) {
            atomicAdd(&g_out_w[cg * 128 + col], s);
            atomicMaxFloat(&g_out_max[cg * 128 + col], mx);
        }
    }
}

__global__ void k_final(float* __restrict__ out) {
    int i = blockIdx.x * 256 + threadIdx.x;
    if (i < NGV * 256) {
        int g = i >> 8, j = i & 255;
        float v;
        if (j < 128) v = g_out_w[g * 128 + j];
        else {
            v = g_out_max[g * 128 + j - 128];
            if (!isfinite(v)) v = 0.f;
        }
        out[i] = v;
    }
}

// ---------------- host orchestration ----------------
#define SYM(p, s) do { void* _t = nullptr; cudaGetSymbolAddress(&_t, s); p = (decltype(p))_t; } while (0)

extern "C" void kernel_launch(void* const* d_in, const int* in_sizes, int n_in,
                              void* d_out, int out_size) {
    const float* x_l    = (const float*)d_in[0];
    const float* x_p    = (const float*)d_in[1];
    const float* ea     = (const float*)d_in[2];
    const int*   esrc   = (const int*)  d_in[3];
    const int*   edst   = (const int*)  d_in[4];
    const int*   lbatch = (const int*)  d_in[5];
    const float* W_node = (const float*)d_in[6];
    const float* W_el   = (const float*)d_in[7];
    const float* Wb     = (const float*)d_in[8];
    const float* bb     = (const float*)d_in[9];
    const float* Wn     = (const float*)d_in[10];
    const float* Ws_    = (const float*)d_in[11];
    const float* bconv  = (const float*)d_in[12];
    const float* W1     = (const float*)d_in[13];
    const float* b1     = (const float*)d_in[14];
    const float* W2     = (const float*)d_in[15];
    const float* b2     = (const float*)d_in[16];
    const float* Wm     = (const float*)d_in[17];
    const float* bm     = (const float*)d_in[18];

    float *xl, *xl2, *xlsum, *prel, *xp, *xp2, *xpsum, *prep, *Abuf, *Bbuf;
    int *dcnt, *dptr, *dedges, *scnt, *sptr, *sedges, *stmp, *bsum;
    SYM(xl, g_xl); SYM(xl2, g_xl2); SYM(xlsum, g_xlsum); SYM(prel, g_prel);
    SYM(xp, g_xp); SYM(xp2, g_xp2); SYM(xpsum, g_xpsum); SYM(prep, g_prep);
    SYM(Abuf, g_A); SYM(Bbuf, g_B);
    SYM(dcnt, g_dst_cnt); SYM(dptr, g_dst_ptr); SYM(dedges, g_dst_edges);
    SYM(scnt, g_src_cnt); SYM(sptr, g_src_ptr); SYM(sedges, g_src_edges);
    SYM(stmp, g_scan_tmp); SYM(bsum, g_bsum);

    // node embedding
    k_embed<<<(NLV + 3) / 4, 128>>>(x_l, xl, W_node, NLV);
    k_embed<<<(NPV + 3) / 4, 128>>>(x_p, xp, W_node, NPV);

    // rbf + cvec
    k_rbf<<<(EV + 255) / 256, 256>>>(ea);
    k_cvec<<<2, 256>>>(W_el, W1);

    // CSR (dst and src)
    cudaMemsetAsync(dcnt, 0, NPV * sizeof(int));
    cudaMemsetAsync(scnt, 0, NLV * sizeof(int));
    k_hist<<<(EV + 255) / 256, 256>>>(esrc, edst);
    int nbp = (NPV + 1023) / 1024, nbl = (NLV + 1023) / 1024;
    k_scan1<<<nbp, 1024>>>(dcnt, stmp, bsum, NPV);
    k_scan2<<<1, 1>>>(bsum, nbp);
    k_scan3<<<nbp, 1024>>>(stmp, bsum, dptr, NPV);
    k_scan1<<<nbl, 1024>>>(scnt, stmp, bsum, NLV);
    k_scan2<<<1, 1>>>(bsum, nbl);
    k_scan3<<<nbl, 1024>>>(stmp, bsum, sptr, NLV);
    cudaMemsetAsync(dcnt, 0, NPV * sizeof(int));
    cudaMemsetAsync(scnt, 0, NLV * sizeof(int));
    k_fill<<<(EV + 255) / 256, 256>>>(esrc, edst);

    // running sums
    cudaMemsetAsync(xlsum, 0, (size_t)NLV * 128 * sizeof(float));
    cudaMemsetAsync(xpsum, 0, (size_t)NPV * 128 * sizeof(float));

    // 3 hetero layers
    float *cxl = xl, *cxp = xp, *nxl = xl2, *nxp = xp2;
    for (int l = 0; l < 3; l++) {
        int ilp = 2 * l, ipl = 2 * l + 1;
        // pre_p: protein-side aggregation (dst CSR, partner = src, x = ligand)
        k_agg<<<(NPV * 32 + 255) / 256, 256>>>(dptr, dedges, esrc, cxl,
                Wb + ilp * 1024, bb + ilp * 128, prep, NPV);
        // pre_l: ligand-side aggregation (src CSR, partner = dst, x = protein)
        k_agg<<<(NLV * 32 + 255) / 256, 256>>>(sptr, sedges, edst, cxp,
                Wb + ipl * 1024, bb + ipl * 128, prel, NLV);
        // xp_new = lrelu(xp@Ws + pre_p@Wn + b); xpsum += xp_new
        k_gemm<<<dim3(1, (NPV + 63) / 64), 256>>>(cxp, Ws_ + (size_t)ilp * 16384,
                prep, Wn + (size_t)ilp * 16384, bconv + ilp * 128,
                nxp, xpsum, NPV, 128, 128, 128, 1);
        // xl_new = lrelu(xl@Ws + pre_l@Wn + b); xlsum += xl_new
        k_gemm<<<dim3(1, (NLV + 63) / 64), 256>>>(cxl, Ws_ + (size_t)ipl * 16384,
                prel, Wn + (size_t)ipl * 16384, bconv + ipl * 128,
                nxl, xlsum, NLV, 128, 128, 128, 1);
        float* t;
        t = cxl; cxl = nxl; nxl = t;
        t = cxp; cxp = nxp; nxp = t;
    }

    // edge readout factorization
    k_gemm<<<dim3(4, (NLV + 63) / 64), 256>>>(xlsum, W1, nullptr, nullptr, b1,
            Abuf, nullptr, NLV, 512, 128, 0, 0);
    k_gemm<<<dim3(4, (NPV + 63) / 64), 256>>>(xpsum, W1 + (size_t)128 * 512,
            nullptr, nullptr, nullptr, Bbuf, nullptr, NPV, 512, 128, 0, 0);

    k_init_out<<<(NGV * 128 + 255) / 256, 256>>>();
    k_edge<<<(EV + 63) / 64, 256>>>(Abuf, Bbuf, W2, b2, Wm, bm, esrc, edst, ea, lbatch);
    k_final<<<(NGV * 256 + 255) / 256, 256>>>((float*)d_out);
}

// round 5
// speedup vs baseline: 1.0000x; 1.0000x over previous
#include <cuda_runtime.h>
#include <math.h>

#define NLV 50000
#define NPV 150000
#define EV  500000
#define NGV 256

// ---------------- device-global scratch (module-load allocated; no runtime alloc) ----
__device__ float g_xl   [NLV*128];
__device__ float g_xl2  [NLV*128];
__device__ float g_xlsum[NLV*128];
__device__ float g_prel [NLV*128];
__device__ float g_xp   [NPV*128];
__device__ float g_xp2  [NPV*128];
__device__ float g_xpsum[NPV*128];
__device__ float g_prep [NPV*128];
__device__ float g_rbf  [EV*8];
__device__ float g_A    [(size_t)NLV*512];
__device__ float g_B    [(size_t)NPV*512];
__device__ float g_cvec [512];
__device__ int   g_dst_cnt[NPV];
__device__ int   g_dst_ptr[NPV+1];
__device__ int   g_dst_edges[EV];
__device__ int   g_src_cnt[NLV];
__device__ int   g_src_ptr[NLV+1];
__device__ int   g_src_edges[EV];
__device__ int   g_scan_tmp[NPV];
__device__ int   g_bsum[512];
__device__ float g_out_w  [NGV*128];
__device__ float g_out_max[NGV*128];

// ---------------- helpers ----------------
__device__ __forceinline__ void atomicMaxFloat(float* addr, float v) {
    if (v >= 0.0f) atomicMax((int*)addr, __float_as_int(v));
    else           atomicMin((unsigned int*)addr, __float_as_uint(v));
}

// ---------------- node embedding: Y[M,128] = X[M,44] @ Wnode[44,128] --------------
__global__ void k_embed(const float* __restrict__ X, float* __restrict__ Y,
                        const float* __restrict__ Wn, int M) {
    __shared__ float xs[4][44];
    int r0 = blockIdx.x * 4;
    int tid = threadIdx.x;  // 128
    for (int i = tid; i < 4 * 44; i += 128) {
        int rr = i / 44, kk = i % 44;
        xs[rr][kk] = (r0 + rr < M) ? X[(size_t)(r0 + rr) * 44 + kk] : 0.f;
    }
    __syncthreads();
    int col = tid;
    #pragma unroll
    for (int rr = 0; rr < 4; rr++) {
        if (r0 + rr < M) {
            float s = 0.f;
            #pragma unroll
            for (int kk = 0; kk < 44; kk++) s = fmaf(xs[rr][kk], Wn[kk * 128 + col], s);
            Y[(size_t)(r0 + rr) * 128 + col] = s;
        }
    }
}

// ---------------- RBF: mu_k = 5k/7, 1/sigma = 1.6 --------------------------------
__global__ void k_rbf(const float* __restrict__ ea) {
    int e = blockIdx.x * 256 + threadIdx.x;
    if (e < EV) {
        float d = ea[e];
        #pragma unroll
        for (int k = 0; k < 8; k++) {
            float t = (d - (5.0f / 7.0f) * (float)k) * 1.6f;
            g_rbf[e * 8 + k] = __expf(-t * t);
        }
    }
}

// ---------------- CSR construction ----------------
__global__ void k_hist(const int* __restrict__ src, const int* __restrict__ dst) {
    int e = blockIdx.x * 256 + threadIdx.x;
    if (e < EV) {
        atomicAdd(&g_dst_cnt[dst[e]], 1);
        atomicAdd(&g_src_cnt[src[e]], 1);
    }
}
__global__ void k_scan1(const int* __restrict__ cnt, int* __restrict__ excl,
                        int* __restrict__ bsum, int n) {
    __shared__ int s[1024];
    int i = blockIdx.x * 1024 + threadIdx.x;
    int v = (i < n) ? cnt[i] : 0;
    s[threadIdx.x] = v;
    __syncthreads();
    for (int off = 1; off < 1024; off <<= 1) {
        int t = 0;
        if ((int)threadIdx.x >= off) t = s[threadIdx.x - off];
        __syncthreads();
        s[threadIdx.x] += t;
        __syncthreads();
    }
    if (i < n) excl[i] = s[threadIdx.x] - v;
    if (threadIdx.x == 1023) bsum[blockIdx.x] = s[1023];
}
__global__ void k_scan2(int* bsum, int nb) {
    if (threadIdx.x == 0 && blockIdx.x == 0) {
        int acc = 0;
        for (int b = 0; b < nb; b++) { int t = bsum[b]; bsum[b] = acc; acc += t; }
    }
}
__global__ void k_scan3(const int* __restrict__ excl, const int* __restrict__ bsum,
                        int* __restrict__ ptr, int n) {
    int i = blockIdx.x * 1024 + threadIdx.x;
    if (i < n) ptr[i] = excl[i] + bsum[i >> 10];
    if (i == 0) ptr[n] = EV;
}
__global__ void k_fill(const int* __restrict__ src, const int* __restrict__ dst) {
    int e = blockIdx.x * 256 + threadIdx.x;
    if (e < EV) {
        int d = dst[e]; int p = atomicAdd(&g_dst_cnt[d], 1); g_dst_edges[g_dst_ptr[d] + p] = e;
        int s = src[e]; int q = atomicAdd(&g_src_cnt[s], 1); g_src_edges[g_src_ptr[s] + q] = e;
    }
}

// ---------------- aggregation: pre[w] = mean_e silu(rbf@Wb+bb) * xsrc[partner(e)] --
__global__ __launch_bounds__(256) void k_agg(
    const int* __restrict__ ptr, const int* __restrict__ eidx,
    const int* __restrict__ partner, const float* __restrict__ xsrc,
    const float* __restrict__ Wb_i, const float* __restrict__ bb_i,
    float* __restrict__ pre, int n_dst)
{
    int w = (blockIdx.x * blockDim.x + threadIdx.x) >> 5;
    int lane = threadIdx.x & 31;
    if (w >= n_dst) return;
    float wreg[8][4], bias[4], acc[4] = {0.f, 0.f, 0.f, 0.f};
    #pragma unroll
    for (int c = 0; c < 4; c++) {
        bias[c] = bb_i[c * 32 + lane];
        #pragma unroll
        for (int k = 0; k < 8; k++) wreg[k][c] = Wb_i[k * 128 + c * 32 + lane];
    }
    int s = ptr[w], e = ptr[w + 1];
    for (int p = s; p < e; p++) {
        int ed = eidx[p];
        float rv = (lane < 8) ? g_rbf[ed * 8 + lane] : 0.f;
        float r[8];
        #pragma unroll
        for (int k = 0; k < 8; k++) r[k] = __shfl_sync(0xffffffffu, rv, k);
        const float* xr = xsrc + (size_t)partner[ed] * 128;
        #pragma unroll
        for (int c = 0; c < 4; c++) {
            float t = bias[c];
            #pragma unroll
            for (int k = 0; k < 8; k++) t = fmaf(r[k], wreg[k][c], t);
            float sg = 1.f / (1.f + __expf(-t));
            acc[c] += (t * sg) * xr[c * 32 + lane];
        }
    }
    float inv = 1.f / (float)((e - s) > 1 ? (e - s) : 1);
    #pragma unroll
    for (int c = 0; c < 4; c++) pre[(size_t)w * 128 + c * 32 + lane] = acc[c] * inv;
}

// ---------------- generic fused SGEMM ----------------
// C[M,N] = act( A0[M,K0]@W0[K0,N] + A1[M,K1]@W1[K1,N] + bias ); optional sum += C
// tile 64x128, BK=16, 256 threads, 8x4 micro. N multiple of 128, K0/K1 multiples of 16.
__global__ __launch_bounds__(256) void k_gemm(
    const float* __restrict__ A0, const float* __restrict__ W0,
    const float* __restrict__ A1, const float* __restrict__ W1,
    const float* __restrict__ bias, float* __restrict__ C,
    float* __restrict__ sum, int M, int N, int K0, int K1, int act)
{
    __shared__ float As[16][68];
    __shared__ float Ws[16][128];
    int tid = threadIdx.x;
    int m0 = blockIdx.y * 64;
    int n0 = blockIdx.x * 128;
    int K = K0 + K1;
    float acc[8][4];
    #pragma unroll
    for (int r = 0; r < 8; r++)
        #pragma unroll
        for (int c = 0; c < 4; c++) acc[r][c] = 0.f;

    int le = tid >> 2;
    int lk = (tid & 3) * 4;
    int arow = m0 + le;
    int ty = tid >> 5, tx = tid & 31;
    int wr = tid >> 7, wc = tid & 127;

    for (int k = 0; k < K; k += 16) {
        const float* Ab; const float* Wb_; int kl; int stride;
        if (k < K0) { Ab = A0; Wb_ = W0; kl = k; stride = K0; }
        else        { Ab = A1; Wb_ = W1; kl = k - K0; stride = K1; }
        float4 a4 = make_float4(0.f, 0.f, 0.f, 0.f);
        if (arow < M) a4 = *(const float4*)(Ab + (size_t)arow * stride + kl + lk);
        As[lk + 0][le] = a4.x; As[lk + 1][le] = a4.y;
        As[lk + 2][le] = a4.z; As[lk + 3][le] = a4.w;
        #pragma unroll
        for (int i = 0; i < 8; i++) {
            int r = wr + 2 * i;
            Ws[r][wc] = Wb_[(size_t)(kl + r) * N + n0 + wc];
        }
        __syncthreads();
        #pragma unroll
        for (int kk = 0; kk < 16; kk++) {
            float4 v0 = *(const float4*)&As[kk][ty * 8];
            float4 v1 = *(const float4*)&As[kk][ty * 8 + 4];
            float a[8] = {v0.x, v0.y, v0.z, v0.w, v1.x, v1.y, v1.z, v1.w};
            float b[4];
            #pragma unroll
            for (int c = 0; c < 4; c++) b[c] = Ws[kk][tx + 32 * c];
            #pragma unroll
            for (int r = 0; r < 8; r++)
                #pragma unroll
                for (int c = 0; c < 4; c++) acc[r][c] = fmaf(a[r], b[c], acc[r][c]);
        }
        __syncthreads();
    }
    #pragma unroll
    for (int r = 0; r < 8; r++) {
        int row = m0 + ty * 8 + r;
        if (row < M) {
            #pragma unroll
            for (int c = 0; c < 4; c++) {
                int col = n0 + tx + 32 * c;
                float v = acc[r][c];
                if (bias) v += bias[col];
                if (act == 1) v = (v >= 0.f) ? v : 0.01f * v;
                C[(size_t)row * N + col] = v;
                if (sum) sum[(size_t)row * N + col] += v;
            }
        }
    }
}

// ---------------- cvec[j] = sum_k W_el[k] * W1[256+k][j] ----------------
__global__ void k_cvec(const float* __restrict__ W_el, const float* __restrict__ W1) {
    int j = blockIdx.x * 256 + threadIdx.x;
    if (j < 512) {
        float s = 0.f;
        #pragma unroll
        for (int k = 0; k < 8; k++) s = fmaf(W_el[k], W1[(size_t)(256 + k) * 512 + j], s);
        g_cvec[j] = s;
    }
}

__global__ void k_init_out() {
    int i = blockIdx.x * 256 + threadIdx.x;
    if (i < NGV * 128) { g_out_w[i] = 0.f; g_out_max[i] = -INFINITY; }
}

// ---------------- fused edge MLP + per-graph reduction ----------------
// per tile of 64 edges (src-CSR order, batch-monotone):
//   h[e,k] = relu(A[src][k] + B[dst][k] + d_e*cvec[k])   (k<512, b1 folded into A)
//   m = h @ W2 + b2 ; w = tanh(m @ Wm + bm)
//   out_w[g] += w*m (segmented) ; out_max[g] = max(m)
__global__ __launch_bounds__(256) void k_edge(
    const float* __restrict__ Al, const float* __restrict__ Bp,
    const float* __restrict__ W2, const float* __restrict__ b2,
    const float* __restrict__ Wm, const float* __restrict__ bm,
    const int* __restrict__ src, const int* __restrict__ dst,
    const float* __restrict__ ea, const int* __restrict__ lbatch)
{
    __shared__ float As[16][68];
    __shared__ float Ws[16][128];
    __shared__ float sm[64][129];
    __shared__ int se_a[64], se_b[64], se_g[64];
    __shared__ float se_d[64];
    __shared__ float cs[512];

    int tid = threadIdx.x;
    int t0 = blockIdx.x * 64;
    if (tid < 64) {
        int slot = t0 + tid;
        if (slot < EV) {
            int e = g_src_edges[slot];
            int s = src[e];
            se_a[tid] = s; se_b[tid] = dst[e];
            se_d[tid] = ea[e];
            se_g[tid] = lbatch[s];
        } else { se_a[tid] = 0; se_b[tid] = 0; se_d[tid] = 0.f; se_g[tid] = -1; }
    }
    for (int i = tid; i < 512; i += 256) cs[i] = g_cvec[i];
    __syncthreads();

    int le = tid >> 2;
    int lk = (tid & 3) * 4;
    const float* arow = Al + (size_t)se_a[le] * 512;
    const float* brow = Bp + (size_t)se_b[le] * 512;
    float dv = se_d[le];

    int ty = tid >> 5, tx = tid & 31;
    int eb = ty * 8;
    int wr = tid >> 7, wc = tid & 127;

    float acc[8][4];
    #pragma unroll
    for (int r = 0; r < 8; r++)
        #pragma unroll
        for (int c = 0; c < 4; c++) acc[r][c] = 0.f;

    // ---- GEMM 1: m = h @ W2, h built on the fly ----
    for (int k = 0; k < 512; k += 16) {
        float4 a4 = *(const float4*)(arow + k + lk);
        float4 b4 = *(const float4*)(brow + k + lk);
        float4 c4 = *(const float4*)(cs + k + lk);
        As[lk + 0][le] = fmaxf(a4.x + b4.x + dv * c4.x, 0.f);
        As[lk + 1][le] = fmaxf(a4.y + b4.y + dv * c4.y, 0.f);
        As[lk + 2][le] = fmaxf(a4.z + b4.z + dv * c4.z, 0.f);
        As[lk + 3][le] = fmaxf(a4.w + b4.w + dv * c4.w, 0.f);
        #pragma unroll
        for (int i = 0; i < 8; i++) {
            int r = wr + 2 * i;
            Ws[r][wc] = W2[(size_t)(k + r) * 128 + wc];
        }
        __syncthreads();
        #pragma unroll
        for (int kk = 0; kk < 16; kk++) {
            float4 v0 = *(const float4*)&As[kk][eb];
            float4 v1 = *(const float4*)&As[kk][eb + 4];
            float a[8] = {v0.x, v0.y, v0.z, v0.w, v1.x, v1.y, v1.z, v1.w};
            float b[4];
            #pragma unroll
            for (int c = 0; c < 4; c++) b[c] = Ws[kk][tx + 32 * c];
            #pragma unroll
            for (int r = 0; r < 8; r++)
                #pragma unroll
                for (int c = 0; c < 4; c++) acc[r][c] = fmaf(a[r], b[c], acc[r][c]);
        }
        __syncthreads();
    }

    // m = acc + b2 ; keep in regs and stage to shared for the second GEMM
    float m[8][4];
    #pragma unroll
    for (int r = 0; r < 8; r++)
        #pragma unroll
        for (int c = 0; c < 4; c++) {
            m[r][c] = acc[r][c] + b2[tx + 32 * c];
            sm[eb + r][tx + 32 * c] = m[r][c];
            acc[r][c] = 0.f;
        }
    __syncthreads();

    // ---- GEMM 2: w = tanh(m @ Wm + bm) ----
    for (int k = 0; k < 128; k += 16) {
        #pragma unroll
        for (int i = 0; i < 8; i++) {
            int r = wr + 2 * i;
            Ws[r][wc] = Wm[(size_t)(k + r) * 128 + wc];
        }
        __syncthreads();
        #pragma unroll
        for (int kk = 0; kk < 16; kk++) {
            float b[4];
            #pragma unroll
            for (int c = 0; c < 4; c++) b[c] = Ws[kk][tx + 32 * c];
            #pragma unroll
            for (int r = 0; r < 8; r++) {
                float a = sm[eb + r][k + kk];
                #pragma unroll
                for (int c = 0; c < 4; c++) acc[r][c] = fmaf(a, b[c], acc[r][c]);
            }
        }
        __syncthreads();
    }

    // ---- segmented per-graph reduction (edges contiguous per thread) ----
    #pragma unroll
    for (int c = 0; c < 4; c++) {
        int col = tx + 32 * c;
        float bmv = bm[col];
        float s = 0.f, mx = -INFINITY;
        int cg = se_g[eb];
        #pragma unroll
        for (int r = 0; r < 8; r++) {
            int g = se_g[eb + r];
            if (g != cg) {
                if (cg >= 0) {
                    atomicAdd(&g_out_w[cg * 128 + col], s);
                    atomicMaxFloat(&g_out_max[cg * 128 + col], mx);
                }
                cg = g; s = 0.f; mx = -INFINITY;
            }
            float w = tanhf(acc[r][c] + bmv);
            s += w * m[r][c];
            mx = fmaxf(mx, m[r][c]);
        }
        if (cg >= 0) {
            atomicAdd(&g_out_w[cg * 128 + col], s);
            atomicMaxFloat(&g_out_max[cg * 128 + col], mx);
        }
    }
}

__global__ void k_final(float* __restrict__ out) {
    int i = blockIdx.x * 256 + threadIdx.x;
    if (i < NGV * 256) {
        int g = i >> 8, j = i & 255;
        float v;
        if (j < 128) v = g_out_w[g * 128 + j];
        else {
            v = g_out_max[g * 128 + j - 128];
            if (!isfinite(v)) v = 0.f;
        }
        out[i] = v;
    }
}

// ---------------- host orchestration ----------------
#define SYM(p, s) do { void* _t = nullptr; cudaGetSymbolAddress(&_t, s); p = (decltype(p))_t; } while (0)

extern "C" void kernel_launch(void* const* d_in, const int* in_sizes, int n_in,
                              void* d_out, int out_size) {
    const float* x_l    = (const float*)d_in[0];
    const float* x_p    = (const float*)d_in[1];
    const float* ea     = (const float*)d_in[2];
    const int*   esrc   = (const int*)  d_in[3];
    const int*   edst   = (const int*)  d_in[4];
    const int*   lbatch = (const int*)  d_in[5];
    const float* W_node = (const float*)d_in[6];
    const float* W_el   = (const float*)d_in[7];
    const float* Wb     = (const float*)d_in[8];
    const float* bb     = (const float*)d_in[9];
    const float* Wn     = (const float*)d_in[10];
    const float* Ws_    = (const float*)d_in[11];
    const float* bconv  = (const float*)d_in[12];
    const float* W1     = (const float*)d_in[13];
    const float* b1     = (const float*)d_in[14];
    const float* W2     = (const float*)d_in[15];
    const float* b2     = (const float*)d_in[16];
    const float* Wm     = (const float*)d_in[17];
    const float* bm     = (const float*)d_in[18];

    float *xl, *xl2, *xlsum, *prel, *xp, *xp2, *xpsum, *prep, *Abuf, *Bbuf;
    int *dcnt, *dptr, *dedges, *scnt, *sptr, *sedges, *stmp, *bsum;
    SYM(xl, g_xl); SYM(xl2, g_xl2); SYM(xlsum, g_xlsum); SYM(prel, g_prel);
    SYM(xp, g_xp); SYM(xp2, g_xp2); SYM(xpsum, g_xpsum); SYM(prep, g_prep);
    SYM(Abuf, g_A); SYM(Bbuf, g_B);
    SYM(dcnt, g_dst_cnt); SYM(dptr, g_dst_ptr); SYM(dedges, g_dst_edges);
    SYM(scnt, g_src_cnt); SYM(sptr, g_src_ptr); SYM(sedges, g_src_edges);
    SYM(stmp, g_scan_tmp); SYM(bsum, g_bsum);

    // node embedding
    k_embed<<<(NLV + 3) / 4, 128>>>(x_l, xl, W_node, NLV);
    k_embed<<<(NPV + 3) / 4, 128>>>(x_p, xp, W_node, NPV);

    // rbf + cvec
    k_rbf<<<(EV + 255) / 256, 256>>>(ea);
    k_cvec<<<2, 256>>>(W_el, W1);

    // CSR (dst and src)
    cudaMemsetAsync(dcnt, 0, NPV * sizeof(int));
    cudaMemsetAsync(scnt, 0, NLV * sizeof(int));
    k_hist<<<(EV + 255) / 256, 256>>>(esrc, edst);
    int nbp = (NPV + 1023) / 1024, nbl = (NLV + 1023) / 1024;
    k_scan1<<<nbp, 1024>>>(dcnt, stmp, bsum, NPV);
    k_scan2<<<1, 1>>>(bsum, nbp);
    k_scan3<<<nbp, 1024>>>(stmp, bsum, dptr, NPV);
    k_scan1<<<nbl, 1024>>>(scnt, stmp, bsum, NLV);
    k_scan2<<<1, 1>>>(bsum, nbl);
    k_scan3<<<nbl, 1024>>>(stmp, bsum, sptr, NLV);
    cudaMemsetAsync(dcnt, 0, NPV * sizeof(int));
    cudaMemsetAsync(scnt, 0, NLV * sizeof(int));
    k_fill<<<(EV + 255) / 256, 256>>>(esrc, edst);

    // running sums
    cudaMemsetAsync(xlsum, 0, (size_t)NLV * 128 * sizeof(float));
    cudaMemsetAsync(xpsum, 0, (size_t)NPV * 128 * sizeof(float));

    // 3 hetero layers
    float *cxl = xl, *cxp = xp, *nxl = xl2, *nxp = xp2;
    for (int l = 0; l < 3; l++) {
        int ilp = 2 * l, ipl = 2 * l + 1;
        // pre_p: protein-side aggregation (dst CSR, partner = src, x = ligand)
        k_agg<<<(NPV * 32 + 255) / 256, 256>>>(dptr, dedges, esrc, cxl,
                Wb + ilp * 1024, bb + ilp * 128, prep, NPV);
        // pre_l: ligand-side aggregation (src CSR, partner = dst, x = protein)
        k_agg<<<(NLV * 32 + 255) / 256, 256>>>(sptr, sedges, edst, cxp,
                Wb + ipl * 1024, bb + ipl * 128, prel, NLV);
        // xp_new = lrelu(xp@Ws + pre_p@Wn + b); xpsum += xp_new
        k_gemm<<<dim3(1, (NPV + 63) / 64), 256>>>(cxp, Ws_ + (size_t)ilp * 16384,
                prep, Wn + (size_t)ilp * 16384, bconv + ilp * 128,
                nxp, xpsum, NPV, 128, 128, 128, 1);
        // xl_new = lrelu(xl@Ws + pre_l@Wn + b); xlsum += xl_new
        k_gemm<<<dim3(1, (NLV + 63) / 64), 256>>>(cxl, Ws_ + (size_t)ipl * 16384,
                prel, Wn + (size_t)ipl * 16384, bconv + ipl * 128,
                nxl, xlsum, NLV, 128, 128, 128, 1);
        float* t;
        t = cxl; cxl = nxl; nxl = t;
        t = cxp; cxp = nxp; nxp = t;
    }

    // edge readout factorization
    k_gemm<<<dim3(4, (NLV + 63) / 64), 256>>>(xlsum, W1, nullptr, nullptr, b1,
            Abuf, nullptr, NLV, 512, 128, 0, 0);
    k_gemm<<<dim3(4, (NPV + 63) / 64), 256>>>(xpsum, W1 + (size_t)128 * 512,
            nullptr, nullptr, nullptr, Bbuf, nullptr, NPV, 512, 128, 0, 0);

    k_init_out<<<(NGV * 128 + 255) / 256, 256>>>();
    k_edge<<<(EV + 63) / 64, 256>>>(Abuf, Bbuf, W2, b2, Wm, bm, esrc, edst, ea, lbatch);
    k_final<<<(NGV * 256 + 255) / 256, 256>>>((float*)d_out);
}